// round 9
// baseline (speedup 1.0000x reference)
#include <cuda_runtime.h>
#include <cuda.h>
#include <cuda_bf16.h>
#include <cstdint>

// ---------------- arch feature detection ----------------
#if defined(__CUDA_ARCH__)
#  if defined(__CUDA_ARCH_FEAT_SM103_ALL) || defined(__CUDA_ARCH_FEAT_SM100_ALL) || \
      (defined(__CUDA_ARCH_SPECIFIC__) && (__CUDA_ARCH_SPECIFIC__ >= 1000)) || \
      (defined(__CUDA_ARCH_FAMILY_SPECIFIC__) && (__CUDA_ARCH_FAMILY_SPECIFIC__ >= 1000))
#    define HAS_TCGEN05 1
#  else
#    define HAS_TCGEN05 0
#  endif
#else
#  define HAS_TCGEN05 0
#endif

// ---------------- problem dims ----------------
#define BB 16
#define CC 64
#define HH 112
#define WW 112
#define NN 256
#define HP 114
#define WP 144
#define C2 128
#define NTILES 896          // BB * HH/2
#define NSM 148

// ---------------- device scratch ----------------
static __device__ __align__(1024) __nv_bfloat16 g_xp[(size_t)BB * HP * WP * C2]; // ~67 MB
static __device__ __align__(1024) __nv_bfloat16 g_wk[9 * NN * C2];               // ~590 KB
static __device__ float g_cn[NN];
static __device__ int g_mode = 2;   // 0: addr-phase recipe, 1: explicit-bo recipe, 2: fallback

// ---------------- PTX helpers ----------------
__device__ __forceinline__ uint32_t smem_to_u32(const void* smem_ptr) {
    uint32_t addr;
    asm("{ .reg .u64 tmp; cvta.to.shared.u64 tmp, %1; cvt.u32.u64 %0, tmp; }"
        : "=r"(addr) : "l"(smem_ptr));
    return addr;
}

#define MBARRIER_INIT(mbar_smem_addr, count) \
    asm volatile("mbarrier.init.shared.b64 [%0], %1;" \
        :: "r"((uint32_t)(mbar_smem_addr)), "r"((uint32_t)(count)) : "memory")
#define MBARRIER_EXPECT_TX(mbar_smem_addr, tx_bytes) \
    asm volatile("mbarrier.arrive.expect_tx.shared.b64 _, [%0], %1;" \
        :: "r"((uint32_t)(mbar_smem_addr)), "r"((uint32_t)(tx_bytes)) : "memory")
#define MBARRIER_ARRIVE(mbar_smem_addr) \
    asm volatile("mbarrier.arrive.shared.b64 _, [%0];" \
        :: "r"((uint32_t)(mbar_smem_addr)) : "memory")

#define MBARRIER_WAIT_PARITY(mbar_smem_addr, phase_parity) do { \
    uint32_t _mbar = (uint32_t)(mbar_smem_addr); \
    uint32_t _parity = (uint32_t)(phase_parity); \
    uint32_t _done; \
    asm volatile( \
        "{\n\t.reg .pred p;\n\t" \
        "mbarrier.try_wait.parity.acquire.cta.shared::cta.b64 p, [%1], %2;\n\t" \
        "selp.b32 %0, 1, 0, p;\n\t}" \
        : "=r"(_done) : "r"(_mbar), "r"(_parity) : "memory"); \
    if (!_done) { \
        asm volatile( \
            "{\n\t.reg .pred P1;\n\t" \
            "WAIT_LOOP_%=:\n\t" \
            "mbarrier.try_wait.parity.acquire.cta.shared::cta.b64 P1, [%0], %1, 0x989680;\n\t" \
            "@P1 bra.uni WAIT_DONE_%=;\n\t" \
            "bra.uni WAIT_LOOP_%=;\n\t" \
            "WAIT_DONE_%=:\n\t}" \
            :: "r"(_mbar), "r"(_parity) : "memory"); \
    } \
} while (0)

#define TMA_LOAD_3D(smem_addr, tensor_map, coord_x, coord_y, coord_z, mbar_smem_addr) \
    asm volatile( \
        "cp.async.bulk.tensor.3d.shared::cta.global.tile.mbarrier::complete_tx::bytes " \
        "[%0], [%1, {%2, %3, %4}], [%5];" \
        :: "r"((uint32_t)(smem_addr)), "l"(tensor_map), \
           "r"((int32_t)(coord_x)), "r"((int32_t)(coord_y)), "r"((int32_t)(coord_z)), \
           "r"((uint32_t)(mbar_smem_addr)) : "memory")

#if HAS_TCGEN05
#define TCGEN05_ALLOC(smem_result_addr, nCols) \
    asm volatile("tcgen05.alloc.cta_group::1.sync.aligned.shared::cta.b32 [%0], %1;" \
        :: "r"((uint32_t)(smem_result_addr)), "r"((uint32_t)(nCols)) : "memory")
#define TCGEN05_DEALLOC(tmem_addr, nCols) \
    asm volatile("tcgen05.dealloc.cta_group::1.sync.aligned.b32 %0, %1;" \
        :: "r"(tmem_addr), "r"((uint32_t)(nCols)))
#define TCGEN05_RELINQUISH_ALLOC_PERMIT() \
    asm volatile("tcgen05.relinquish_alloc_permit.cta_group::1.sync.aligned;")
#define TCGEN05_COMMIT(mbar_smem_addr) \
    asm volatile("tcgen05.commit.cta_group::1.mbarrier::arrive::one.shared::cluster.b64 [%0];" \
        :: "r"((uint32_t)(mbar_smem_addr)) : "memory")
#define TCGEN05_FENCE_AFTER() \
    asm volatile("tcgen05.fence::after_thread_sync;" ::: "memory")
#define TCGEN05_FENCE_BEFORE() \
    asm volatile("tcgen05.fence::before_thread_sync;" ::: "memory")
#define TCGEN05_WAIT_LD() \
    asm volatile("tcgen05.wait::ld.sync.aligned;" ::: "memory")
#define FENCE_PROXY_ASYNC() \
    asm volatile("fence.proxy.async.shared::cta;" ::: "memory")

#define TCGEN05_LD_32X32B_X32(r, tmem_addr) \
    asm volatile( \
        "tcgen05.ld.sync.aligned.32x32b.x32.b32 " \
        "{%0, %1, %2, %3, %4, %5, %6, %7, " \
        " %8, %9, %10, %11, %12, %13, %14, %15, " \
        " %16, %17, %18, %19, %20, %21, %22, %23, " \
        " %24, %25, %26, %27, %28, %29, %30, %31}, [%32];" \
        : "=r"((r)[0]),  "=r"((r)[1]),  "=r"((r)[2]),  "=r"((r)[3]), \
          "=r"((r)[4]),  "=r"((r)[5]),  "=r"((r)[6]),  "=r"((r)[7]), \
          "=r"((r)[8]),  "=r"((r)[9]),  "=r"((r)[10]), "=r"((r)[11]), \
          "=r"((r)[12]), "=r"((r)[13]), "=r"((r)[14]), "=r"((r)[15]), \
          "=r"((r)[16]), "=r"((r)[17]), "=r"((r)[18]), "=r"((r)[19]), \
          "=r"((r)[20]), "=r"((r)[21]), "=r"((r)[22]), "=r"((r)[23]), \
          "=r"((r)[24]), "=r"((r)[25]), "=r"((r)[26]), "=r"((r)[27]), \
          "=r"((r)[28]), "=r"((r)[29]), "=r"((r)[30]), "=r"((r)[31]) \
        : "r"(tmem_addr))

static constexpr uint64_t SMEM_DESC_BASE_SW128 =
    (uint64_t(2) << 61) | (uint64_t(1) << 46) | (uint64_t(64) << 32) | (uint64_t(1) << 16);
#define MAKE_SMEM_DESC(base_addr) \
    (SMEM_DESC_BASE_SW128 | ((uint64_t)((base_addr) >> 4) & 0x3FFF))

__device__ __forceinline__ void mma_f16_ss(uint32_t d_tmem, uint64_t a_desc, uint64_t b_desc,
                                           uint32_t idesc, bool acc) {
    uint32_t en = acc ? 1u : 0u;
    asm volatile(
        "{\n\t.reg .pred p;\n\t"
        "setp.ne.u32 p, %5, 0;\n\t"
        "tcgen05.mma.cta_group::1.kind::f16 [%0], %1, %2, %3, {%4, %4, %4, %4}, p;\n\t}"
        :: "r"(d_tmem), "l"(a_desc), "l"(b_desc), "r"(idesc), "r"(0u), "r"(en)
        : "memory");
}
#endif  // HAS_TCGEN05

// ---------------- preprocessing kernels ----------------
__global__ void sim_fill_xp(const float* __restrict__ x) {
    __shared__ float tile[64][33];
    int pw0 = blockIdx.x * 32;
    int py = blockIdx.y;
    int b = blockIdx.z;
    int lane = threadIdx.x & 31, warp = threadIdx.x >> 5;
    int h = py - 1;
    bool rowvalid = (py >= 1 && py <= WW);
    int w = pw0 + lane - 1;
#pragma unroll
    for (int k = 0; k < 8; k++) {
        int c = warp * 8 + k;
        float v = 0.f;
        if (rowvalid && w >= 0 && w < WW)
            v = x[(((size_t)b * CC + c) * HH + h) * WW + w];
        tile[c][lane] = v;
    }
    __syncthreads();
    int p = threadIdx.x >> 3, cg = threadIdx.x & 7;
    int pw = pw0 + p;
    if (pw < WP) {
        __nv_bfloat16* dst = g_xp + (((size_t)b * HP + py) * WP + pw) * C2;
        __nv_bfloat162 sq[4], xv[4];
#pragma unroll
        for (int t = 0; t < 4; t++) {
            float v0 = tile[cg * 8 + 2 * t][p];
            float v1 = tile[cg * 8 + 2 * t + 1][p];
            sq[t] = __floats2bfloat162_rn(v0 * v0, v1 * v1);
            xv[t] = __floats2bfloat162_rn(v0, v1);
        }
        *reinterpret_cast<uint4*>(dst + cg * 8) = *reinterpret_cast<const uint4*>(sq);
        *reinterpret_cast<uint4*>(dst + 64 + cg * 8) = *reinterpret_cast<const uint4*>(xv);
    }
}

__global__ void sim_prep_w(const float* __restrict__ sw, const float* __restrict__ tm) {
    int n = blockIdx.x, c = threadIdx.x;
    float csum = 0.f;
#pragma unroll
    for (int p = 0; p < 3; p++)
#pragma unroll
        for (int q = 0; q < 3; q++) {
            size_t idx = (((size_t)n * CC + c) * 3 + p) * 3 + q;
            float w = fabsf(sw[idx]);
            float t = tm[idx];
            csum += w * t * t;
            size_t o = ((size_t)(p * 3 + q) * NN + n) * C2;
            g_wk[o + c] = __float2bfloat16(-w);
            g_wk[o + 64 + c] = __float2bfloat16(2.f * w * t);
        }
    __shared__ float red[64];
    red[c] = csum;
    __syncthreads();
    for (int s = 32; s > 0; s >>= 1) {
        if (c < s) red[c] += red[c + s];
        __syncthreads();
    }
    if (c == 0) g_cn[n] = red[0];
}

// ---------------- descriptor-semantics probe ----------------
__global__ void sim_probe() {
#if HAS_TCGEN05
    __shared__ __align__(1024) char ps[23040];
    __shared__ int err[2];
    uint32_t sb = smem_to_u32(ps);
    int tid = threadIdx.x, wid = tid >> 5, lane = tid & 31;
    if (tid == 0) { err[0] = 0; err[1] = 0; MBARRIER_INIT(sb + 16, 1); }
    if (wid == 0) { TCGEN05_ALLOC(sb + 0, 128); TCGEN05_RELINQUISH_ALLOC_PERMIT(); }
    __syncthreads();
    uint32_t tmem;
    asm volatile("ld.shared.b32 %0, [%1];" : "=r"(tmem) : "r"(sb));

    for (int px = tid; px < 136; px += 128) {
        for (int c = 0; c < 8; c++) {
            __align__(16) __nv_bfloat16 v[8];
#pragma unroll
            for (int e = 0; e < 8; e++) {
                int ch = c * 8 + e;
                v[e] = __float2bfloat16((float)((px * 7 + ch * 13) % 23 - 11));
            }
            *reinterpret_cast<uint4*>(ps + 1024 + px * 128 + ((c ^ (px & 7)) * 16)) =
                *reinterpret_cast<const uint4*>(v);
        }
    }
    for (int n = tid; n < 32; n += 128) {
        for (int c = 0; c < 8; c++) {
            __align__(16) __nv_bfloat16 v[8];
#pragma unroll
            for (int e = 0; e < 8; e++)
                v[e] = __float2bfloat16((c * 8 + e == n) ? 1.f : 0.f);
            *reinterpret_cast<uint4*>(ps + 18432 + n * 128 + ((c ^ (n & 7)) * 16)) =
                *reinterpret_cast<const uint4*>(v);
        }
    }
    __syncthreads();
    FENCE_PROXY_ASYNC();

    const uint32_t idesc = (1u << 4) | (1u << 7) | (1u << 10) | (4u << 17) | (8u << 24);
    uint64_t bdesc = MAKE_SMEM_DESC(sb + 18432);
    for (int cand = 0; cand < 2; cand++) {
        if (tid == 0) {
            uint64_t ad = MAKE_SMEM_DESC(sb + 1024) + 8 + (cand ? (1ull << 48) : 0);
#pragma unroll
            for (int kk = 0; kk < 4; kk++)
                mma_f16_ss(tmem + cand * 64, ad + 2 * kk, bdesc + 2 * kk, idesc, kk > 0);
            TCGEN05_COMMIT(sb + 16);
        }
        __syncthreads();
        MBARRIER_WAIT_PARITY(sb + 16, cand);
        TCGEN05_FENCE_AFTER();
        uint32_t r[32];
        TCGEN05_LD_32X32B_X32(r, tmem + cand * 64);
        TCGEN05_WAIT_LD();
        int px = wid * 32 + lane + 1;
        int bad = 0;
#pragma unroll
        for (int n = 0; n < 32; n++) {
            float expv = (float)((px * 7 + n * 13) % 23 - 11);
            if (__uint_as_float(r[n]) != expv) bad = 1;
        }
        if (bad) atomicAdd(&err[cand], 1);
        __syncthreads();
    }
    if (tid == 0) g_mode = (err[0] == 0) ? 0 : ((err[1] == 0) ? 1 : 2);
    TCGEN05_FENCE_BEFORE();
    __syncthreads();
    if (wid == 0) TCGEN05_DEALLOC(tmem, 128);
#else
    if (threadIdx.x == 0) g_mode = 2;
#endif
}

// ---------------- main conv kernel (persistent) ----------------
// Grid = 148 CTAs x 320 threads. Warps 0-7: epilogue. tid 256: TMA producer.
// tid 288: MMA consumer. Each CTA loops tiles t = bid + ti*148 (row-pairs).
// Per tile: sliding 3-row A window (R8 scheme), 18 substages (pq,kh),
// B = 32KB, 3-deep ring continuous across tiles. Epilogue(t) overlaps
// producer's A/B prefetch for t+1; consumer waits EPI_DONE before t+1 MMAs.
#define SM_BAR_BFULL 16    // 3 x 8B : 16..40
#define SM_BAR_BEMPT 40    // 3 x 8B : 40..64
#define SM_BAR_A0    64
#define SM_BAR_A1    72
#define SM_BAR_AFREE 80
#define SM_BAR_DONE  88
#define SM_BAR_EPI   96
#define SM_ABASE     1024
#define A_ENTRY      17408
#define A_DATA       16640            // 130 px * 128B
#define SM_BRING     (SM_ABASE + 6 * A_ENTRY)   // 105472
#define B_STAGE      32768
#define NB           3
#define NSUB         18
// mode-2: stages of 64KB at SM_ABASE (B 32K | A0 16K | A1 16K), 3 deep
#define M2_STAGE     65536
#define M2_OFFA0     32768
#define M2_OFFA1     49152
#define CONV_SMEM    (SM_BRING + NB * B_STAGE)  // 203776
#define NTHREADS     320

#if HAS_TCGEN05
static constexpr uint32_t CONV_IDESC =
    (1u << 4) | (1u << 7) | (1u << 10) | ((NN / 8) << 17) | ((128 / 16) << 24);
#endif

__global__ void __launch_bounds__(NTHREADS, 1) sim_conv(
    const __grid_constant__ CUtensorMap tmx130,
    const __grid_constant__ CUtensorMap tmx128,
    const __grid_constant__ CUtensorMap tmw256,
    float* __restrict__ out)
{
    extern __shared__ char smem[];
    uint32_t sb = smem_to_u32(smem);
    int tid = threadIdx.x, wid = tid >> 5, lane = tid & 31;
    int bid = blockIdx.x;
    int ntiles = (NTILES - bid + NSM - 1) / NSM;

    if (tid == 0) {
#pragma unroll
        for (int s = 0; s < NB; s++) {
            MBARRIER_INIT(sb + SM_BAR_BFULL + s * 8, 1);
            MBARRIER_INIT(sb + SM_BAR_BEMPT + s * 8, 1);
        }
        MBARRIER_INIT(sb + SM_BAR_A0, 1);
        MBARRIER_INIT(sb + SM_BAR_A1, 1);
        MBARRIER_INIT(sb + SM_BAR_AFREE, 1);
        MBARRIER_INIT(sb + SM_BAR_DONE, 1);
        MBARRIER_INIT(sb + SM_BAR_EPI, 8);
    }

#if HAS_TCGEN05
    if (wid == 0) {
        TCGEN05_ALLOC(sb + 512, 512);
        TCGEN05_RELINQUISH_ALLOC_PERMIT();
    }
    __syncthreads();

    uint32_t tmem;
    asm volatile("ld.shared.b32 %0, [%1];" : "=r"(tmem) : "r"(sb + 512));
    int mode = g_mode;

    if (tid == 256) {
        // ================= producer =================
        int gs = 0;
        for (int ti = 0; ti < ntiles; ti++) {
            int t = bid + ti * NSM;
            int b = t / (HH / 2), i0 = (t % (HH / 2)) * 2;
            int zbase = b * HP + i0;
            int tp = ti & 1;
            if (mode < 2) {
                // A slots free only after tile ti-1's MMAs complete
                if (ti > 0) MBARRIER_WAIT_PARITY(sb + SM_BAR_DONE, (ti - 1) & 1);
                MBARRIER_EXPECT_TX(sb + SM_BAR_A0, 6 * A_DATA);
#pragma unroll
                for (int e = 0; e < 6; e++)
                    TMA_LOAD_3D(sb + SM_ABASE + e * A_ENTRY, &tmx130,
                                64 * (e & 1), 0, zbase + (e >> 1), sb + SM_BAR_A0);
                // B substages 0..8
                for (int s = 0; s < 9; s++, gs++) {
                    int st = gs % NB;
                    if (gs >= NB)
                        MBARRIER_WAIT_PARITY(sb + SM_BAR_BEMPT + st * 8,
                                             ((gs - NB) / NB) & 1);
                    MBARRIER_EXPECT_TX(sb + SM_BAR_BFULL + st * 8, B_STAGE);
                    TMA_LOAD_3D(sb + SM_BRING + st * B_STAGE, &tmw256,
                                64 * (s & 1), 0, s >> 1, sb + SM_BAR_BFULL + st * 8);
                }
                // row 3 into slots 0,1 after p=0 substages drain
                MBARRIER_WAIT_PARITY(sb + SM_BAR_AFREE, tp);
                MBARRIER_EXPECT_TX(sb + SM_BAR_A1, 2 * A_DATA);
#pragma unroll
                for (int kh = 0; kh < 2; kh++)
                    TMA_LOAD_3D(sb + SM_ABASE + kh * A_ENTRY, &tmx130,
                                64 * kh, 0, zbase + 3, sb + SM_BAR_A1);
                // B substages 9..17
                for (int s = 9; s < NSUB; s++, gs++) {
                    int st = gs % NB;
                    MBARRIER_WAIT_PARITY(sb + SM_BAR_BEMPT + st * 8,
                                         ((gs - NB) / NB) & 1);
                    MBARRIER_EXPECT_TX(sb + SM_BAR_BFULL + st * 8, B_STAGE);
                    TMA_LOAD_3D(sb + SM_BRING + st * B_STAGE, &tmw256,
                                64 * (s & 1), 0, s >> 1, sb + SM_BAR_BFULL + st * 8);
                }
            } else {
                for (int s = 0; s < NSUB; s++, gs++) {
                    int st = gs % NB;
                    if (gs >= NB)
                        MBARRIER_WAIT_PARITY(sb + SM_BAR_BEMPT + st * 8,
                                             ((gs - NB) / NB) & 1);
                    int pq = s >> 1, kh = s & 1;
                    int p = pq / 3, q = pq % 3;
                    uint32_t sbase = sb + SM_ABASE + st * M2_STAGE;
                    uint32_t bar = sb + SM_BAR_BFULL + st * 8;
                    MBARRIER_EXPECT_TX(bar, 32768 + 2 * 16384);
                    TMA_LOAD_3D(sbase, &tmw256, 64 * kh, 0, pq, bar);
                    TMA_LOAD_3D(sbase + M2_OFFA0, &tmx128, 64 * kh, q, zbase + p, bar);
                    TMA_LOAD_3D(sbase + M2_OFFA1, &tmx128, 64 * kh, q, zbase + p + 1, bar);
                }
            }
        }
    } else if (tid == 288) {
        // ================= MMA consumer =================
        int gs = 0;
        for (int ti = 0; ti < ntiles; ti++) {
            int tp = ti & 1;
            if (mode < 2) MBARRIER_WAIT_PARITY(sb + SM_BAR_A0, tp);
            if (ti > 0) {
                // previous tile's epilogue must finish reading TMEM
                MBARRIER_WAIT_PARITY(sb + SM_BAR_EPI, (ti - 1) & 1);
                TCGEN05_FENCE_AFTER();
            }
            for (int s = 0; s < NSUB; s++, gs++) {
                int st = gs % NB;
                int ph = (gs / NB) & 1;
                if (mode < 2 && s == 12) MBARRIER_WAIT_PARITY(sb + SM_BAR_A1, tp);
                MBARRIER_WAIT_PARITY(sb + SM_BAR_BFULL + st * 8, ph);
                uint64_t a0, a1, bd;
                if (mode < 2) {
                    int pq = s >> 1, kh = s & 1;
                    int p = pq / 3, q = pq % 3;
                    bd = MAKE_SMEM_DESC(sb + SM_BRING + st * B_STAGE);
                    int slot0 = (p % 3) * 2 + kh;
                    int slot1 = (((p + 1) % 3) * 2) + kh;
                    uint64_t qadd = (uint64_t)(q * 8) +
                                    (mode == 1 ? ((uint64_t)q << 48) : 0);
                    a0 = MAKE_SMEM_DESC(sb + SM_ABASE + slot0 * A_ENTRY) + qadd;
                    a1 = MAKE_SMEM_DESC(sb + SM_ABASE + slot1 * A_ENTRY) + qadd;
                } else {
                    uint32_t sbase = sb + SM_ABASE + st * M2_STAGE;
                    bd = MAKE_SMEM_DESC(sbase);
                    a0 = MAKE_SMEM_DESC(sbase + M2_OFFA0);
                    a1 = MAKE_SMEM_DESC(sbase + M2_OFFA1);
                }
#pragma unroll
                for (int kk = 0; kk < 4; kk++) {
                    bool acc = !(s == 0 && kk == 0);
                    mma_f16_ss(tmem,       a0 + 2 * kk, bd + 2 * kk, CONV_IDESC, acc);
                    mma_f16_ss(tmem + 256, a1 + 2 * kk, bd + 2 * kk, CONV_IDESC, acc);
                }
                TCGEN05_COMMIT(sb + SM_BAR_BEMPT + st * 8);
                if (mode < 2 && s == 5) TCGEN05_COMMIT(sb + SM_BAR_AFREE);
            }
            TCGEN05_COMMIT(sb + SM_BAR_DONE);
        }
    } else if (wid < 8) {
        // ================= epilogue workers =================
        int r = wid >> 2;
        int jj = (wid & 3) * 32 + lane;
        uint32_t dbase = tmem + r * 256;
        for (int ti = 0; ti < ntiles; ti++) {
            int t = bid + ti * NSM;
            int b = t / (HH / 2), i0 = (t % (HH / 2)) * 2;
            int i = i0 + r;
            MBARRIER_WAIT_PARITY(sb + SM_BAR_DONE, ti & 1);
            TCGEN05_FENCE_AFTER();
            for (int c0 = 0; c0 < NN; c0 += 32) {
                uint32_t reg[32];
                TCGEN05_LD_32X32B_X32(reg, dbase + c0);
                TCGEN05_WAIT_LD();
                if (jj < WW) {
                    float* po = out + (((size_t)(b * NN + c0)) * HH + i) * WW + jj;
#pragma unroll
                    for (int c = 0; c < 32; c++)
                        po[(size_t)c * (HH * WW)] =
                            __uint_as_float(reg[c]) - __ldg(&g_cn[c0 + c]);
                }
            }
            TCGEN05_FENCE_BEFORE();
            if (lane == 0) MBARRIER_ARRIVE(sb + SM_BAR_EPI);
        }
    }

    __syncthreads();
    if (wid == 0) TCGEN05_DEALLOC(tmem, 512);

#else
    // -------- compile-only fallback for plain sm_103 --------
    __syncthreads();
    const float* cn_g = g_cn;
    for (int ti = 0; ti < ntiles; ti++) {
        int t = bid + ti * NSM;
        int b = t / (HH / 2), i0 = (t % (HH / 2)) * 2;
        for (int e = tid; e < 2 * NN * WW; e += NTHREADS) {
            int j = e % WW;
            int n = (e / WW) % NN;
            int r = e / (WW * NN);
            int i = i0 + r;
            float acc = 0.f;
            for (int p = 0; p < 3; p++)
                for (int q = 0; q < 3; q++) {
                    const __nv_bfloat16* a =
                        g_xp + (((size_t)b * HP + (i + p)) * WP + (j + q)) * C2;
                    const __nv_bfloat16* wv = g_wk + ((size_t)(p * 3 + q) * NN + n) * C2;
                    for (int c = 0; c < C2; c++)
                        acc += __bfloat162float(a[c]) * __bfloat162float(wv[c]);
                }
            out[(((size_t)(b * NN + n)) * HH + i) * WW + j] = acc - cn_g[n];
        }
    }
#endif
}

// ---------------- host launcher ----------------
typedef CUresult (*PFN_encodeTiled)(
    CUtensorMap*, CUtensorMapDataType, cuuint32_t, void*,
    const cuuint64_t*, const cuuint64_t*, const cuuint32_t*, const cuuint32_t*,
    CUtensorMapInterleave, CUtensorMapSwizzle, CUtensorMapL2promotion,
    CUtensorMapFloatOOBfill);

extern "C" void kernel_launch(void* const* d_in, const int* in_sizes, int n_in,
                              void* d_out, int out_size) {
    const float* x  = (const float*)d_in[0];
    const float* sw = (const float*)d_in[1];
    const float* tm = (const float*)d_in[2];
    float* out = (float*)d_out;

    static PFN_encodeTiled enc = nullptr;
    if (!enc) {
        void* fp = nullptr;
        cudaDriverEntryPointQueryResult qr;
        cudaGetDriverEntryPoint("cuTensorMapEncodeTiled", &fp, cudaEnableDefault, &qr);
        enc = (PFN_encodeTiled)fp;
    }
    if (!enc) return;

    void* xp_ptr = nullptr;
    void* wk_ptr = nullptr;
    cudaGetSymbolAddress(&xp_ptr, g_xp);
    cudaGetSymbolAddress(&wk_ptr, g_wk);

    CUtensorMap tmx130, tmx128, tmw256;
    {
        cuuint64_t dims[3]    = {C2, WP, (cuuint64_t)BB * HP};
        cuuint64_t strides[2] = {(cuuint64_t)C2 * 2, (cuuint64_t)WP * C2 * 2};
        cuuint32_t es[3]      = {1, 1, 1};
        cuuint32_t box130[3]  = {64, 130, 1};
        cuuint32_t box128[3]  = {64, 128, 1};
        enc(&tmx130, CU_TENSOR_MAP_DATA_TYPE_BFLOAT16, 3, xp_ptr, dims, strides, box130, es,
            CU_TENSOR_MAP_INTERLEAVE_NONE, CU_TENSOR_MAP_SWIZZLE_128B,
            CU_TENSOR_MAP_L2_PROMOTION_L2_128B, CU_TENSOR_MAP_FLOAT_OOB_FILL_NONE);
        enc(&tmx128, CU_TENSOR_MAP_DATA_TYPE_BFLOAT16, 3, xp_ptr, dims, strides, box128, es,
            CU_TENSOR_MAP_INTERLEAVE_NONE, CU_TENSOR_MAP_SWIZZLE_128B,
            CU_TENSOR_MAP_L2_PROMOTION_L2_128B, CU_TENSOR_MAP_FLOAT_OOB_FILL_NONE);
    }
    {
        cuuint64_t dims[3]    = {C2, NN, 9};
        cuuint64_t strides[2] = {(cuuint64_t)C2 * 2, (cuuint64_t)NN * C2 * 2};
        cuuint32_t es[3]      = {1, 1, 1};
        cuuint32_t boxf[3]    = {64, 256, 1};
        enc(&tmw256, CU_TENSOR_MAP_DATA_TYPE_BFLOAT16, 3, wk_ptr, dims, strides, boxf, es,
            CU_TENSOR_MAP_INTERLEAVE_NONE, CU_TENSOR_MAP_SWIZZLE_128B,
            CU_TENSOR_MAP_L2_PROMOTION_L2_128B, CU_TENSOR_MAP_FLOAT_OOB_FILL_NONE);
    }

    cudaFuncSetAttribute(sim_conv, cudaFuncAttributeMaxDynamicSharedMemorySize, CONV_SMEM);

    sim_fill_xp<<<dim3(5, HP, BB), 256>>>(x);
    sim_prep_w<<<NN, 64>>>(sw, tm);
    sim_probe<<<1, 128>>>();
    sim_conv<<<NSM, NTHREADS, CONV_SMEM>>>(tmx130, tmx128, tmw256, out);
}

// round 10
// speedup vs baseline: 1.0735x; 1.0735x over previous
#include <cuda_runtime.h>
#include <cuda.h>
#include <cuda_bf16.h>
#include <cstdint>

// ---------------- arch feature detection ----------------
#if defined(__CUDA_ARCH__)
#  if defined(__CUDA_ARCH_FEAT_SM103_ALL) || defined(__CUDA_ARCH_FEAT_SM100_ALL) || \
      (defined(__CUDA_ARCH_SPECIFIC__) && (__CUDA_ARCH_SPECIFIC__ >= 1000)) || \
      (defined(__CUDA_ARCH_FAMILY_SPECIFIC__) && (__CUDA_ARCH_FAMILY_SPECIFIC__ >= 1000))
#    define HAS_TCGEN05 1
#  else
#    define HAS_TCGEN05 0
#  endif
#else
#  define HAS_TCGEN05 0
#endif

// ---------------- problem dims ----------------
#define BB 16
#define CC 64
#define HH 112
#define WW 112
#define NN 256
#define HP 114
#define WP 144
#define C2 128
#define NTILES 896          // BB * HH/2
#define NSM 148

// ---------------- device scratch ----------------
static __device__ __align__(1024) __nv_bfloat16 g_xp[(size_t)BB * HP * WP * C2]; // ~67 MB
static __device__ __align__(1024) __nv_bfloat16 g_wk[9 * NN * C2];               // ~590 KB
static __device__ float g_cn[NN];
static __device__ int g_mode = 2;   // 0: addr-phase recipe, 1: explicit-bo recipe, 2: fallback

// ---------------- PTX helpers ----------------
__device__ __forceinline__ uint32_t smem_to_u32(const void* smem_ptr) {
    uint32_t addr;
    asm("{ .reg .u64 tmp; cvta.to.shared.u64 tmp, %1; cvt.u32.u64 %0, tmp; }"
        : "=r"(addr) : "l"(smem_ptr));
    return addr;
}

#define MBARRIER_INIT(mbar_smem_addr, count) \
    asm volatile("mbarrier.init.shared.b64 [%0], %1;" \
        :: "r"((uint32_t)(mbar_smem_addr)), "r"((uint32_t)(count)) : "memory")
#define MBARRIER_EXPECT_TX(mbar_smem_addr, tx_bytes) \
    asm volatile("mbarrier.arrive.expect_tx.shared.b64 _, [%0], %1;" \
        :: "r"((uint32_t)(mbar_smem_addr)), "r"((uint32_t)(tx_bytes)) : "memory")
#define MBARRIER_ARRIVE(mbar_smem_addr) \
    asm volatile("mbarrier.arrive.shared.b64 _, [%0];" \
        :: "r"((uint32_t)(mbar_smem_addr)) : "memory")

#define MBARRIER_WAIT_PARITY(mbar_smem_addr, phase_parity) do { \
    uint32_t _mbar = (uint32_t)(mbar_smem_addr); \
    uint32_t _parity = (uint32_t)(phase_parity); \
    uint32_t _done; \
    asm volatile( \
        "{\n\t.reg .pred p;\n\t" \
        "mbarrier.try_wait.parity.acquire.cta.shared::cta.b64 p, [%1], %2;\n\t" \
        "selp.b32 %0, 1, 0, p;\n\t}" \
        : "=r"(_done) : "r"(_mbar), "r"(_parity) : "memory"); \
    if (!_done) { \
        asm volatile( \
            "{\n\t.reg .pred P1;\n\t" \
            "WAIT_LOOP_%=:\n\t" \
            "mbarrier.try_wait.parity.acquire.cta.shared::cta.b64 P1, [%0], %1, 0x989680;\n\t" \
            "@P1 bra.uni WAIT_DONE_%=;\n\t" \
            "bra.uni WAIT_LOOP_%=;\n\t" \
            "WAIT_DONE_%=:\n\t}" \
            :: "r"(_mbar), "r"(_parity) : "memory"); \
    } \
} while (0)

#define TMA_LOAD_3D(smem_addr, tensor_map, coord_x, coord_y, coord_z, mbar_smem_addr) \
    asm volatile( \
        "cp.async.bulk.tensor.3d.shared::cta.global.tile.mbarrier::complete_tx::bytes " \
        "[%0], [%1, {%2, %3, %4}], [%5];" \
        :: "r"((uint32_t)(smem_addr)), "l"(tensor_map), \
           "r"((int32_t)(coord_x)), "r"((int32_t)(coord_y)), "r"((int32_t)(coord_z)), \
           "r"((uint32_t)(mbar_smem_addr)) : "memory")

#if HAS_TCGEN05
#define TCGEN05_ALLOC(smem_result_addr, nCols) \
    asm volatile("tcgen05.alloc.cta_group::1.sync.aligned.shared::cta.b32 [%0], %1;" \
        :: "r"((uint32_t)(smem_result_addr)), "r"((uint32_t)(nCols)) : "memory")
#define TCGEN05_DEALLOC(tmem_addr, nCols) \
    asm volatile("tcgen05.dealloc.cta_group::1.sync.aligned.b32 %0, %1;" \
        :: "r"(tmem_addr), "r"((uint32_t)(nCols)))
#define TCGEN05_RELINQUISH_ALLOC_PERMIT() \
    asm volatile("tcgen05.relinquish_alloc_permit.cta_group::1.sync.aligned;")
#define TCGEN05_COMMIT(mbar_smem_addr) \
    asm volatile("tcgen05.commit.cta_group::1.mbarrier::arrive::one.shared::cluster.b64 [%0];" \
        :: "r"((uint32_t)(mbar_smem_addr)) : "memory")
#define TCGEN05_FENCE_AFTER() \
    asm volatile("tcgen05.fence::after_thread_sync;" ::: "memory")
#define TCGEN05_FENCE_BEFORE() \
    asm volatile("tcgen05.fence::before_thread_sync;" ::: "memory")
#define TCGEN05_WAIT_LD() \
    asm volatile("tcgen05.wait::ld.sync.aligned;" ::: "memory")
#define FENCE_PROXY_ASYNC() \
    asm volatile("fence.proxy.async.shared::cta;" ::: "memory")

#define TCGEN05_LD_32X32B_X32(r, tmem_addr) \
    asm volatile( \
        "tcgen05.ld.sync.aligned.32x32b.x32.b32 " \
        "{%0, %1, %2, %3, %4, %5, %6, %7, " \
        " %8, %9, %10, %11, %12, %13, %14, %15, " \
        " %16, %17, %18, %19, %20, %21, %22, %23, " \
        " %24, %25, %26, %27, %28, %29, %30, %31}, [%32];" \
        : "=r"((r)[0]),  "=r"((r)[1]),  "=r"((r)[2]),  "=r"((r)[3]), \
          "=r"((r)[4]),  "=r"((r)[5]),  "=r"((r)[6]),  "=r"((r)[7]), \
          "=r"((r)[8]),  "=r"((r)[9]),  "=r"((r)[10]), "=r"((r)[11]), \
          "=r"((r)[12]), "=r"((r)[13]), "=r"((r)[14]), "=r"((r)[15]), \
          "=r"((r)[16]), "=r"((r)[17]), "=r"((r)[18]), "=r"((r)[19]), \
          "=r"((r)[20]), "=r"((r)[21]), "=r"((r)[22]), "=r"((r)[23]), \
          "=r"((r)[24]), "=r"((r)[25]), "=r"((r)[26]), "=r"((r)[27]), \
          "=r"((r)[28]), "=r"((r)[29]), "=r"((r)[30]), "=r"((r)[31]) \
        : "r"(tmem_addr))

static constexpr uint64_t SMEM_DESC_BASE_SW128 =
    (uint64_t(2) << 61) | (uint64_t(1) << 46) | (uint64_t(64) << 32) | (uint64_t(1) << 16);
#define MAKE_SMEM_DESC(base_addr) \
    (SMEM_DESC_BASE_SW128 | ((uint64_t)((base_addr) >> 4) & 0x3FFF))

__device__ __forceinline__ void mma_f16_ss(uint32_t d_tmem, uint64_t a_desc, uint64_t b_desc,
                                           uint32_t idesc, bool acc) {
    uint32_t en = acc ? 1u : 0u;
    asm volatile(
        "{\n\t.reg .pred p;\n\t"
        "setp.ne.u32 p, %5, 0;\n\t"
        "tcgen05.mma.cta_group::1.kind::f16 [%0], %1, %2, %3, {%4, %4, %4, %4}, p;\n\t}"
        :: "r"(d_tmem), "l"(a_desc), "l"(b_desc), "r"(idesc), "r"(0u), "r"(en)
        : "memory");
}
#endif  // HAS_TCGEN05

// ---------------- preprocessing kernels ----------------
__global__ void sim_fill_xp(const float* __restrict__ x) {
    __shared__ float tile[64][33];
    int pw0 = blockIdx.x * 32;
    int py = blockIdx.y;
    int b = blockIdx.z;
    int lane = threadIdx.x & 31, warp = threadIdx.x >> 5;
    int h = py - 1;
    bool rowvalid = (py >= 1 && py <= WW);
    int w = pw0 + lane - 1;
#pragma unroll
    for (int k = 0; k < 8; k++) {
        int c = warp * 8 + k;
        float v = 0.f;
        if (rowvalid && w >= 0 && w < WW)
            v = x[(((size_t)b * CC + c) * HH + h) * WW + w];
        tile[c][lane] = v;
    }
    __syncthreads();
    int p = threadIdx.x >> 3, cg = threadIdx.x & 7;
    int pw = pw0 + p;
    if (pw < WP) {
        __nv_bfloat16* dst = g_xp + (((size_t)b * HP + py) * WP + pw) * C2;
        __nv_bfloat162 sq[4], xv[4];
#pragma unroll
        for (int t = 0; t < 4; t++) {
            float v0 = tile[cg * 8 + 2 * t][p];
            float v1 = tile[cg * 8 + 2 * t + 1][p];
            sq[t] = __floats2bfloat162_rn(v0 * v0, v1 * v1);
            xv[t] = __floats2bfloat162_rn(v0, v1);
        }
        *reinterpret_cast<uint4*>(dst + cg * 8) = *reinterpret_cast<const uint4*>(sq);
        *reinterpret_cast<uint4*>(dst + 64 + cg * 8) = *reinterpret_cast<const uint4*>(xv);
    }
}

__global__ void sim_prep_w(const float* __restrict__ sw, const float* __restrict__ tm) {
    int n = blockIdx.x, c = threadIdx.x;
    float csum = 0.f;
#pragma unroll
    for (int p = 0; p < 3; p++)
#pragma unroll
        for (int q = 0; q < 3; q++) {
            size_t idx = (((size_t)n * CC + c) * 3 + p) * 3 + q;
            float w = fabsf(sw[idx]);
            float t = tm[idx];
            csum += w * t * t;
            size_t o = ((size_t)(p * 3 + q) * NN + n) * C2;
            g_wk[o + c] = __float2bfloat16(-w);
            g_wk[o + 64 + c] = __float2bfloat16(2.f * w * t);
        }
    __shared__ float red[64];
    red[c] = csum;
    __syncthreads();
    for (int s = 32; s > 0; s >>= 1) {
        if (c < s) red[c] += red[c + s];
        __syncthreads();
    }
    if (c == 0) g_cn[n] = red[0];
}

// ---------------- descriptor-semantics probe ----------------
__global__ void sim_probe() {
#if HAS_TCGEN05
    __shared__ __align__(1024) char ps[23040];
    __shared__ int err[2];
    uint32_t sb = smem_to_u32(ps);
    int tid = threadIdx.x, wid = tid >> 5, lane = tid & 31;
    if (tid == 0) { err[0] = 0; err[1] = 0; MBARRIER_INIT(sb + 16, 1); }
    if (wid == 0) { TCGEN05_ALLOC(sb + 0, 128); TCGEN05_RELINQUISH_ALLOC_PERMIT(); }
    __syncthreads();
    uint32_t tmem;
    asm volatile("ld.shared.b32 %0, [%1];" : "=r"(tmem) : "r"(sb));

    for (int px = tid; px < 136; px += 128) {
        for (int c = 0; c < 8; c++) {
            __align__(16) __nv_bfloat16 v[8];
#pragma unroll
            for (int e = 0; e < 8; e++) {
                int ch = c * 8 + e;
                v[e] = __float2bfloat16((float)((px * 7 + ch * 13) % 23 - 11));
            }
            *reinterpret_cast<uint4*>(ps + 1024 + px * 128 + ((c ^ (px & 7)) * 16)) =
                *reinterpret_cast<const uint4*>(v);
        }
    }
    for (int n = tid; n < 32; n += 128) {
        for (int c = 0; c < 8; c++) {
            __align__(16) __nv_bfloat16 v[8];
#pragma unroll
            for (int e = 0; e < 8; e++)
                v[e] = __float2bfloat16((c * 8 + e == n) ? 1.f : 0.f);
            *reinterpret_cast<uint4*>(ps + 18432 + n * 128 + ((c ^ (n & 7)) * 16)) =
                *reinterpret_cast<const uint4*>(v);
        }
    }
    __syncthreads();
    FENCE_PROXY_ASYNC();

    const uint32_t idesc = (1u << 4) | (1u << 7) | (1u << 10) | (4u << 17) | (8u << 24);
    uint64_t bdesc = MAKE_SMEM_DESC(sb + 18432);
    for (int cand = 0; cand < 2; cand++) {
        if (tid == 0) {
            uint64_t ad = MAKE_SMEM_DESC(sb + 1024) + 8 + (cand ? (1ull << 48) : 0);
#pragma unroll
            for (int kk = 0; kk < 4; kk++)
                mma_f16_ss(tmem + cand * 64, ad + 2 * kk, bdesc + 2 * kk, idesc, kk > 0);
            TCGEN05_COMMIT(sb + 16);
        }
        __syncthreads();
        MBARRIER_WAIT_PARITY(sb + 16, cand);
        TCGEN05_FENCE_AFTER();
        uint32_t r[32];
        TCGEN05_LD_32X32B_X32(r, tmem + cand * 64);
        TCGEN05_WAIT_LD();
        int px = wid * 32 + lane + 1;
        int bad = 0;
#pragma unroll
        for (int n = 0; n < 32; n++) {
            float expv = (float)((px * 7 + n * 13) % 23 - 11);
            if (__uint_as_float(r[n]) != expv) bad = 1;
        }
        if (bad) atomicAdd(&err[cand], 1);
        __syncthreads();
    }
    if (tid == 0) g_mode = (err[0] == 0) ? 0 : ((err[1] == 0) ? 1 : 2);
    TCGEN05_FENCE_BEFORE();
    __syncthreads();
    if (wid == 0) TCGEN05_DEALLOC(tmem, 128);
#else
    if (threadIdx.x == 0) g_mode = 2;
#endif
}

// ---------------- main conv kernel (persistent, TMEM double-buffered) ----------------
// Grid = 148 CTAs x 320 threads. Warps 0-7: epilogue; tid 256: producer; tid 288: consumer.
// Modes 0/1: per tile (row-pair): 8 resident A entries (4 rows x 2 kh), two nh
//   passes of 18 substages (pq,kh) with N=128 MMAs into TMEM buffer nh (256 cols).
//   Epilogue of pass nh overlaps the other pass. B: 16KB pieces, 5-deep ring.
// Mode 2: R9 schedule (N=256, 3x64KB ring, single-buffer, per-tile epilogue).
#define SM_BAR_BFULL 16    // 5 x 8B : 16..56
#define SM_BAR_BEMPT 56    // 5 x 8B : 56..96
#define SM_BAR_A0    96
#define SM_BAR_A1    104
#define SM_BAR_TDONE 112
#define SM_BAR_PDONE 120
#define SM_BAR_EPI0  128
#define SM_BAR_EPI1  136
#define SM_ABASE     1024
#define A_ENTRY      17408
#define A_DATA       16640            // 130 px * 128B
#define SM_BRING     (SM_ABASE + 8 * A_ENTRY)   // 140288
#define B_STAGE      16384
#define NB           5
// mode-2: stages of 64KB at SM_ABASE (B 32K | A0 16K | A1 16K), 3 deep
#define M2_STAGE     65536
#define M2_OFFA0     32768
#define M2_OFFA1     49152
#define CONV_SMEM    (SM_BRING + NB * B_STAGE)  // 222208
#define NTHREADS     320

#if HAS_TCGEN05
static constexpr uint32_t IDESC_N128 =
    (1u << 4) | (1u << 7) | (1u << 10) | ((128 / 8) << 17) | ((128 / 16) << 24);
static constexpr uint32_t IDESC_N256 =
    (1u << 4) | (1u << 7) | (1u << 10) | ((NN / 8) << 17) | ((128 / 16) << 24);
#endif

__global__ void __launch_bounds__(NTHREADS, 1) sim_conv(
    const __grid_constant__ CUtensorMap tmx130,
    const __grid_constant__ CUtensorMap tmx128,
    const __grid_constant__ CUtensorMap tmw128,
    const __grid_constant__ CUtensorMap tmw256,
    float* __restrict__ out)
{
    extern __shared__ char smem[];
    uint32_t sb = smem_to_u32(smem);
    int tid = threadIdx.x, wid = tid >> 5, lane = tid & 31;
    int bid = blockIdx.x;
    int ntiles = (NTILES - bid + NSM - 1) / NSM;

    if (tid == 0) {
#pragma unroll
        for (int s = 0; s < NB; s++) {
            MBARRIER_INIT(sb + SM_BAR_BFULL + s * 8, 1);
            MBARRIER_INIT(sb + SM_BAR_BEMPT + s * 8, 1);
        }
        MBARRIER_INIT(sb + SM_BAR_A0, 1);
        MBARRIER_INIT(sb + SM_BAR_A1, 1);
        MBARRIER_INIT(sb + SM_BAR_TDONE, 1);
        MBARRIER_INIT(sb + SM_BAR_PDONE, 1);
        MBARRIER_INIT(sb + SM_BAR_EPI0, 8);
        MBARRIER_INIT(sb + SM_BAR_EPI1, 8);
    }

#if HAS_TCGEN05
    if (wid == 0) {
        TCGEN05_ALLOC(sb + 512, 512);
        TCGEN05_RELINQUISH_ALLOC_PERMIT();
    }
    __syncthreads();

    uint32_t tmem;
    asm volatile("ld.shared.b32 %0, [%1];" : "=r"(tmem) : "r"(sb + 512));
    int mode = g_mode;

    if (tid == 256) {
        // ================= producer =================
        int gs = 0;
        for (int ti = 0; ti < ntiles; ti++) {
            int t = bid + ti * NSM;
            int b = t / (HH / 2), i0 = (t % (HH / 2)) * 2;
            int zbase = b * HP + i0;
            if (mode < 2) {
                // A slots reusable only after tile ti-1's LAST MMA completes
                if (ti > 0) MBARRIER_WAIT_PARITY(sb + SM_BAR_TDONE, (ti - 1) & 1);
                MBARRIER_EXPECT_TX(sb + SM_BAR_A0, 4 * A_DATA);
#pragma unroll
                for (int e = 0; e < 4; e++)  // rows 0,1
                    TMA_LOAD_3D(sb + SM_ABASE + e * A_ENTRY, &tmx130,
                                64 * (e & 1), 0, zbase + (e >> 1), sb + SM_BAR_A0);
                MBARRIER_EXPECT_TX(sb + SM_BAR_A1, 4 * A_DATA);
#pragma unroll
                for (int e = 4; e < 8; e++)  // rows 2,3
                    TMA_LOAD_3D(sb + SM_ABASE + e * A_ENTRY, &tmx130,
                                64 * (e & 1), 0, zbase + (e >> 1), sb + SM_BAR_A1);
                // 36 B pieces: nh-major, then (pq,kh)
                for (int s = 0; s < 36; s++, gs++) {
                    int st = gs % NB;
                    if (gs >= NB)
                        MBARRIER_WAIT_PARITY(sb + SM_BAR_BEMPT + st * 8,
                                             ((gs - NB) / NB) & 1);
                    int nh = s / 18, ss = s % 18;
                    int pq = ss >> 1, kh = ss & 1;
                    MBARRIER_EXPECT_TX(sb + SM_BAR_BFULL + st * 8, B_STAGE);
                    TMA_LOAD_3D(sb + SM_BRING + st * B_STAGE, &tmw128,
                                64 * kh, 128 * nh, pq, sb + SM_BAR_BFULL + st * 8);
                }
            } else {
                for (int s = 0; s < 18; s++, gs++) {
                    int st = gs % 3;
                    if (gs >= 3)
                        MBARRIER_WAIT_PARITY(sb + SM_BAR_BEMPT + st * 8,
                                             ((gs - 3) / 3) & 1);
                    int pq = s >> 1, kh = s & 1;
                    int p = pq / 3, q = pq % 3;
                    uint32_t sbase = sb + SM_ABASE + st * M2_STAGE;
                    uint32_t bar = sb + SM_BAR_BFULL + st * 8;
                    MBARRIER_EXPECT_TX(bar, 32768 + 2 * 16384);
                    TMA_LOAD_3D(sbase, &tmw256, 64 * kh, 0, pq, bar);
                    TMA_LOAD_3D(sbase + M2_OFFA0, &tmx128, 64 * kh, q, zbase + p, bar);
                    TMA_LOAD_3D(sbase + M2_OFFA1, &tmx128, 64 * kh, q, zbase + p + 1, bar);
                }
            }
        }
    } else if (tid == 288) {
        // ================= MMA consumer =================
        int gs = 0;
        for (int ti = 0; ti < ntiles; ti++) {
            int tp = ti & 1;
            if (mode < 2) {
                for (int nh = 0; nh < 2; nh++) {
                    // buffer nh was drained during previous tile
                    if (ti > 0) {
                        MBARRIER_WAIT_PARITY(
                            sb + (nh ? SM_BAR_EPI1 : SM_BAR_EPI0), (ti - 1) & 1);
                        TCGEN05_FENCE_AFTER();
                    }
                    if (nh == 0) MBARRIER_WAIT_PARITY(sb + SM_BAR_A0, tp);
                    uint32_t d0 = tmem + nh * 256;
                    uint32_t d1 = d0 + 128;
                    for (int s = 0; s < 18; s++, gs++) {
                        if (nh == 0 && s == 6) MBARRIER_WAIT_PARITY(sb + SM_BAR_A1, tp);
                        int st = gs % NB;
                        int ph = (gs / NB) & 1;
                        MBARRIER_WAIT_PARITY(sb + SM_BAR_BFULL + st * 8, ph);
                        int pq = s >> 1, kh = s & 1;
                        int p = pq / 3, q = pq % 3;
                        uint64_t bd = MAKE_SMEM_DESC(sb + SM_BRING + st * B_STAGE);
                        uint64_t qadd = (uint64_t)(q * 8) +
                                        (mode == 1 ? ((uint64_t)q << 48) : 0);
                        uint64_t a0 = MAKE_SMEM_DESC(
                            sb + SM_ABASE + (p * 2 + kh) * A_ENTRY) + qadd;
                        uint64_t a1 = MAKE_SMEM_DESC(
                            sb + SM_ABASE + ((p + 1) * 2 + kh) * A_ENTRY) + qadd;
#pragma unroll
                        for (int kk = 0; kk < 4; kk++) {
                            bool acc = !(s == 0 && kk == 0);
                            mma_f16_ss(d0, a0 + 2 * kk, bd + 2 * kk, IDESC_N128, acc);
                            mma_f16_ss(d1, a1 + 2 * kk, bd + 2 * kk, IDESC_N128, acc);
                        }
                        TCGEN05_COMMIT(sb + SM_BAR_BEMPT + st * 8);
                    }
                    TCGEN05_COMMIT(sb + SM_BAR_PDONE);
                    if (nh == 1) TCGEN05_COMMIT(sb + SM_BAR_TDONE);
                }
            } else {
                if (ti > 0) {
                    MBARRIER_WAIT_PARITY(sb + SM_BAR_EPI0, (ti - 1) & 1);
                    TCGEN05_FENCE_AFTER();
                }
                for (int s = 0; s < 18; s++, gs++) {
                    int st = gs % 3;
                    int ph = (gs / 3) & 1;
                    MBARRIER_WAIT_PARITY(sb + SM_BAR_BFULL + st * 8, ph);
                    uint32_t sbase = sb + SM_ABASE + st * M2_STAGE;
                    uint64_t bd = MAKE_SMEM_DESC(sbase);
                    uint64_t a0 = MAKE_SMEM_DESC(sbase + M2_OFFA0);
                    uint64_t a1 = MAKE_SMEM_DESC(sbase + M2_OFFA1);
#pragma unroll
                    for (int kk = 0; kk < 4; kk++) {
                        bool acc = !(s == 0 && kk == 0);
                        mma_f16_ss(tmem,       a0 + 2 * kk, bd + 2 * kk, IDESC_N256, acc);
                        mma_f16_ss(tmem + 256, a1 + 2 * kk, bd + 2 * kk, IDESC_N256, acc);
                    }
                    TCGEN05_COMMIT(sb + SM_BAR_BEMPT + st * 8);
                }
                TCGEN05_COMMIT(sb + SM_BAR_TDONE);
            }
        }
    } else if (wid < 8) {
        // ================= epilogue workers =================
        int r = wid >> 2;               // output row within pair
        int jj = (wid & 3) * 32 + lane; // pixel (TMEM lane)
        for (int ti = 0; ti < ntiles; ti++) {
            int t = bid + ti * NSM;
            int b = t / (HH / 2), i0 = (t % (HH / 2)) * 2;
            int i = i0 + r;
            if (mode < 2) {
                for (int nh = 0; nh < 2; nh++) {
                    MBARRIER_WAIT_PARITY(sb + SM_BAR_PDONE, nh);  // 0,1,0,1,...
                    TCGEN05_FENCE_AFTER();
                    uint32_t dbase = tmem + nh * 256 + r * 128;
                    for (int ch = 0; ch < 4; ch++) {
                        uint32_t reg[32];
                        TCGEN05_LD_32X32B_X32(reg, dbase + ch * 32);
                        TCGEN05_WAIT_LD();
                        if (jj < WW) {
                            int n0 = nh * 128 + ch * 32;
                            float* po = out + (((size_t)(b * NN + n0)) * HH + i) * WW + jj;
#pragma unroll
                            for (int c = 0; c < 32; c++)
                                po[(size_t)c * (HH * WW)] =
                                    __uint_as_float(reg[c]) - __ldg(&g_cn[n0 + c]);
                        }
                    }
                    TCGEN05_FENCE_BEFORE();
                    if (lane == 0)
                        MBARRIER_ARRIVE(sb + (nh ? SM_BAR_EPI1 : SM_BAR_EPI0));
                }
            } else {
                MBARRIER_WAIT_PARITY(sb + SM_BAR_TDONE, ti & 1);
                TCGEN05_FENCE_AFTER();
                uint32_t dbase = tmem + r * 256;
                for (int c0 = 0; c0 < NN; c0 += 32) {
                    uint32_t reg[32];
                    TCGEN05_LD_32X32B_X32(reg, dbase + c0);
                    TCGEN05_WAIT_LD();
                    if (jj < WW) {
                        float* po = out + (((size_t)(b * NN + c0)) * HH + i) * WW + jj;
#pragma unroll
                        for (int c = 0; c < 32; c++)
                            po[(size_t)c * (HH * WW)] =
                                __uint_as_float(reg[c]) - __ldg(&g_cn[c0 + c]);
                    }
                }
                TCGEN05_FENCE_BEFORE();
                if (lane == 0) MBARRIER_ARRIVE(sb + SM_BAR_EPI0);
            }
        }
    }

    __syncthreads();
    if (wid == 0) TCGEN05_DEALLOC(tmem, 512);

#else
    // -------- compile-only fallback for plain sm_103 --------
    __syncthreads();
    const float* cn_g = g_cn;
    for (int ti = 0; ti < ntiles; ti++) {
        int t = bid + ti * NSM;
        int b = t / (HH / 2), i0 = (t % (HH / 2)) * 2;
        for (int e = tid; e < 2 * NN * WW; e += NTHREADS) {
            int j = e % WW;
            int n = (e / WW) % NN;
            int r = e / (WW * NN);
            int i = i0 + r;
            float acc = 0.f;
            for (int p = 0; p < 3; p++)
                for (int q = 0; q < 3; q++) {
                    const __nv_bfloat16* a =
                        g_xp + (((size_t)b * HP + (i + p)) * WP + (j + q)) * C2;
                    const __nv_bfloat16* wv = g_wk + ((size_t)(p * 3 + q) * NN + n) * C2;
                    for (int c = 0; c < C2; c++)
                        acc += __bfloat162float(a[c]) * __bfloat162float(wv[c]);
                }
            out[(((size_t)(b * NN + n)) * HH + i) * WW + j] = acc - cn_g[n];
        }
    }
#endif
}

// ---------------- host launcher ----------------
typedef CUresult (*PFN_encodeTiled)(
    CUtensorMap*, CUtensorMapDataType, cuuint32_t, void*,
    const cuuint64_t*, const cuuint64_t*, const cuuint32_t*, const cuuint32_t*,
    CUtensorMapInterleave, CUtensorMapSwizzle, CUtensorMapL2promotion,
    CUtensorMapFloatOOBfill);

extern "C" void kernel_launch(void* const* d_in, const int* in_sizes, int n_in,
                              void* d_out, int out_size) {
    const float* x  = (const float*)d_in[0];
    const float* sw = (const float*)d_in[1];
    const float* tm = (const float*)d_in[2];
    float* out = (float*)d_out;

    static PFN_encodeTiled enc = nullptr;
    if (!enc) {
        void* fp = nullptr;
        cudaDriverEntryPointQueryResult qr;
        cudaGetDriverEntryPoint("cuTensorMapEncodeTiled", &fp, cudaEnableDefault, &qr);
        enc = (PFN_encodeTiled)fp;
    }
    if (!enc) return;

    void* xp_ptr = nullptr;
    void* wk_ptr = nullptr;
    cudaGetSymbolAddress(&xp_ptr, g_xp);
    cudaGetSymbolAddress(&wk_ptr, g_wk);

    CUtensorMap tmx130, tmx128, tmw128, tmw256;
    {
        cuuint64_t dims[3]    = {C2, WP, (cuuint64_t)BB * HP};
        cuuint64_t strides[2] = {(cuuint64_t)C2 * 2, (cuuint64_t)WP * C2 * 2};
        cuuint32_t es[3]      = {1, 1, 1};
        cuuint32_t box130[3]  = {64, 130, 1};
        cuuint32_t box128[3]  = {64, 128, 1};
        enc(&tmx130, CU_TENSOR_MAP_DATA_TYPE_BFLOAT16, 3, xp_ptr, dims, strides, box130, es,
            CU_TENSOR_MAP_INTERLEAVE_NONE, CU_TENSOR_MAP_SWIZZLE_128B,
            CU_TENSOR_MAP_L2_PROMOTION_L2_128B, CU_TENSOR_MAP_FLOAT_OOB_FILL_NONE);
        enc(&tmx128, CU_TENSOR_MAP_DATA_TYPE_BFLOAT16, 3, xp_ptr, dims, strides, box128, es,
            CU_TENSOR_MAP_INTERLEAVE_NONE, CU_TENSOR_MAP_SWIZZLE_128B,
            CU_TENSOR_MAP_L2_PROMOTION_L2_128B, CU_TENSOR_MAP_FLOAT_OOB_FILL_NONE);
    }
    {
        cuuint64_t dims[3]    = {C2, NN, 9};
        cuuint64_t strides[2] = {(cuuint64_t)C2 * 2, (cuuint64_t)NN * C2 * 2};
        cuuint32_t es[3]      = {1, 1, 1};
        cuuint32_t boxh[3]    = {64, 128, 1};
        cuuint32_t boxf[3]    = {64, 256, 1};
        enc(&tmw128, CU_TENSOR_MAP_DATA_TYPE_BFLOAT16, 3, wk_ptr, dims, strides, boxh, es,
            CU_TENSOR_MAP_INTERLEAVE_NONE, CU_TENSOR_MAP_SWIZZLE_128B,
            CU_TENSOR_MAP_L2_PROMOTION_L2_128B, CU_TENSOR_MAP_FLOAT_OOB_FILL_NONE);
        enc(&tmw256, CU_TENSOR_MAP_DATA_TYPE_BFLOAT16, 3, wk_ptr, dims, strides, boxf, es,
            CU_TENSOR_MAP_INTERLEAVE_NONE, CU_TENSOR_MAP_SWIZZLE_128B,
            CU_TENSOR_MAP_L2_PROMOTION_L2_128B, CU_TENSOR_MAP_FLOAT_OOB_FILL_NONE);
    }

    cudaFuncSetAttribute(sim_conv, cudaFuncAttributeMaxDynamicSharedMemorySize, CONV_SMEM);

    sim_fill_xp<<<dim3(5, HP, BB), 256>>>(x);
    sim_prep_w<<<NN, 64>>>(sw, tm);
    sim_probe<<<1, 128>>>();
    sim_conv<<<NSM, NTHREADS, CONV_SMEM>>>(tmx130, tmx128, tmw128, tmw256, out);
}

// round 11
// speedup vs baseline: 1.1823x; 1.1014x over previous
#include <cuda_runtime.h>
#include <cuda.h>
#include <cuda_bf16.h>
#include <cstdint>

// ---------------- arch feature detection ----------------
#if defined(__CUDA_ARCH__)
#  if defined(__CUDA_ARCH_FEAT_SM103_ALL) || defined(__CUDA_ARCH_FEAT_SM100_ALL) || \
      (defined(__CUDA_ARCH_SPECIFIC__) && (__CUDA_ARCH_SPECIFIC__ >= 1000)) || \
      (defined(__CUDA_ARCH_FAMILY_SPECIFIC__) && (__CUDA_ARCH_FAMILY_SPECIFIC__ >= 1000))
#    define HAS_TCGEN05 1
#  else
#    define HAS_TCGEN05 0
#  endif
#else
#  define HAS_TCGEN05 0
#endif

// ---------------- problem dims ----------------
#define BB 16
#define CC 64
#define HH 112
#define WW 112
#define NN 256
#define HP 114
#define WP 144
#define C2 128
#define NTILES 896          // row-pairs
#define NT2 1792            // (row-pair, nh) tiles
#define NSM 148

// ---------------- device scratch ----------------
static __device__ __align__(1024) __nv_bfloat16 g_xp[(size_t)BB * HP * WP * C2]; // ~67 MB
static __device__ __align__(1024) __nv_bfloat16 g_wk[9 * NN * C2];               // ~590 KB
static __device__ float g_cn[NN];
static __device__ int g_mode = 2;   // 0: addr-phase recipe, 1: explicit-bo recipe, 2: fallback

// ---------------- PTX helpers ----------------
__device__ __forceinline__ uint32_t smem_to_u32(const void* smem_ptr) {
    uint32_t addr;
    asm("{ .reg .u64 tmp; cvta.to.shared.u64 tmp, %1; cvt.u32.u64 %0, tmp; }"
        : "=r"(addr) : "l"(smem_ptr));
    return addr;
}

#define MBARRIER_INIT(mbar_smem_addr, count) \
    asm volatile("mbarrier.init.shared.b64 [%0], %1;" \
        :: "r"((uint32_t)(mbar_smem_addr)), "r"((uint32_t)(count)) : "memory")
#define MBARRIER_EXPECT_TX(mbar_smem_addr, tx_bytes) \
    asm volatile("mbarrier.arrive.expect_tx.shared.b64 _, [%0], %1;" \
        :: "r"((uint32_t)(mbar_smem_addr)), "r"((uint32_t)(tx_bytes)) : "memory")
#define MBARRIER_ARRIVE(mbar_smem_addr) \
    asm volatile("mbarrier.arrive.shared.b64 _, [%0];" \
        :: "r"((uint32_t)(mbar_smem_addr)) : "memory")

#define MBARRIER_WAIT_PARITY(mbar_smem_addr, phase_parity) do { \
    uint32_t _mbar = (uint32_t)(mbar_smem_addr); \
    uint32_t _parity = (uint32_t)(phase_parity); \
    uint32_t _done; \
    asm volatile( \
        "{\n\t.reg .pred p;\n\t" \
        "mbarrier.try_wait.parity.acquire.cta.shared::cta.b64 p, [%1], %2;\n\t" \
        "selp.b32 %0, 1, 0, p;\n\t}" \
        : "=r"(_done) : "r"(_mbar), "r"(_parity) : "memory"); \
    if (!_done) { \
        asm volatile( \
            "{\n\t.reg .pred P1;\n\t" \
            "WAIT_LOOP_%=:\n\t" \
            "mbarrier.try_wait.parity.acquire.cta.shared::cta.b64 P1, [%0], %1, 0x989680;\n\t" \
            "@P1 bra.uni WAIT_DONE_%=;\n\t" \
            "bra.uni WAIT_LOOP_%=;\n\t" \
            "WAIT_DONE_%=:\n\t}" \
            :: "r"(_mbar), "r"(_parity) : "memory"); \
    } \
} while (0)

#define TMA_LOAD_3D(smem_addr, tensor_map, coord_x, coord_y, coord_z, mbar_smem_addr) \
    asm volatile( \
        "cp.async.bulk.tensor.3d.shared::cta.global.tile.mbarrier::complete_tx::bytes " \
        "[%0], [%1, {%2, %3, %4}], [%5];" \
        :: "r"((uint32_t)(smem_addr)), "l"(tensor_map), \
           "r"((int32_t)(coord_x)), "r"((int32_t)(coord_y)), "r"((int32_t)(coord_z)), \
           "r"((uint32_t)(mbar_smem_addr)) : "memory")

#if HAS_TCGEN05
#define TCGEN05_ALLOC(smem_result_addr, nCols) \
    asm volatile("tcgen05.alloc.cta_group::1.sync.aligned.shared::cta.b32 [%0], %1;" \
        :: "r"((uint32_t)(smem_result_addr)), "r"((uint32_t)(nCols)) : "memory")
#define TCGEN05_DEALLOC(tmem_addr, nCols) \
    asm volatile("tcgen05.dealloc.cta_group::1.sync.aligned.b32 %0, %1;" \
        :: "r"(tmem_addr), "r"((uint32_t)(nCols)))
#define TCGEN05_RELINQUISH_ALLOC_PERMIT() \
    asm volatile("tcgen05.relinquish_alloc_permit.cta_group::1.sync.aligned;")
#define TCGEN05_COMMIT(mbar_smem_addr) \
    asm volatile("tcgen05.commit.cta_group::1.mbarrier::arrive::one.shared::cluster.b64 [%0];" \
        :: "r"((uint32_t)(mbar_smem_addr)) : "memory")
#define TCGEN05_FENCE_AFTER() \
    asm volatile("tcgen05.fence::after_thread_sync;" ::: "memory")
#define TCGEN05_FENCE_BEFORE() \
    asm volatile("tcgen05.fence::before_thread_sync;" ::: "memory")
#define TCGEN05_WAIT_LD() \
    asm volatile("tcgen05.wait::ld.sync.aligned;" ::: "memory")
#define FENCE_PROXY_ASYNC() \
    asm volatile("fence.proxy.async.shared::cta;" ::: "memory")

#define TCGEN05_LD_32X32B_X32(r, tmem_addr) \
    asm volatile( \
        "tcgen05.ld.sync.aligned.32x32b.x32.b32 " \
        "{%0, %1, %2, %3, %4, %5, %6, %7, " \
        " %8, %9, %10, %11, %12, %13, %14, %15, " \
        " %16, %17, %18, %19, %20, %21, %22, %23, " \
        " %24, %25, %26, %27, %28, %29, %30, %31}, [%32];" \
        : "=r"((r)[0]),  "=r"((r)[1]),  "=r"((r)[2]),  "=r"((r)[3]), \
          "=r"((r)[4]),  "=r"((r)[5]),  "=r"((r)[6]),  "=r"((r)[7]), \
          "=r"((r)[8]),  "=r"((r)[9]),  "=r"((r)[10]), "=r"((r)[11]), \
          "=r"((r)[12]), "=r"((r)[13]), "=r"((r)[14]), "=r"((r)[15]), \
          "=r"((r)[16]), "=r"((r)[17]), "=r"((r)[18]), "=r"((r)[19]), \
          "=r"((r)[20]), "=r"((r)[21]), "=r"((r)[22]), "=r"((r)[23]), \
          "=r"((r)[24]), "=r"((r)[25]), "=r"((r)[26]), "=r"((r)[27]), \
          "=r"((r)[28]), "=r"((r)[29]), "=r"((r)[30]), "=r"((r)[31]) \
        : "r"(tmem_addr))

static constexpr uint64_t SMEM_DESC_BASE_SW128 =
    (uint64_t(2) << 61) | (uint64_t(1) << 46) | (uint64_t(64) << 32) | (uint64_t(1) << 16);
#define MAKE_SMEM_DESC(base_addr) \
    (SMEM_DESC_BASE_SW128 | ((uint64_t)((base_addr) >> 4) & 0x3FFF))

__device__ __forceinline__ void mma_f16_ss(uint32_t d_tmem, uint64_t a_desc, uint64_t b_desc,
                                           uint32_t idesc, bool acc) {
    uint32_t en = acc ? 1u : 0u;
    asm volatile(
        "{\n\t.reg .pred p;\n\t"
        "setp.ne.u32 p, %5, 0;\n\t"
        "tcgen05.mma.cta_group::1.kind::f16 [%0], %1, %2, %3, {%4, %4, %4, %4}, p;\n\t}"
        :: "r"(d_tmem), "l"(a_desc), "l"(b_desc), "r"(idesc), "r"(0u), "r"(en)
        : "memory");
}
#endif  // HAS_TCGEN05

// ---------------- preprocessing kernels ----------------
__global__ void sim_fill_xp(const float* __restrict__ x) {
    __shared__ float tile[64][33];
    int pw0 = blockIdx.x * 32;
    int py = blockIdx.y;
    int b = blockIdx.z;
    int lane = threadIdx.x & 31, warp = threadIdx.x >> 5;
    int h = py - 1;
    bool rowvalid = (py >= 1 && py <= WW);
    int w = pw0 + lane - 1;
#pragma unroll
    for (int k = 0; k < 8; k++) {
        int c = warp * 8 + k;
        float v = 0.f;
        if (rowvalid && w >= 0 && w < WW)
            v = x[(((size_t)b * CC + c) * HH + h) * WW + w];
        tile[c][lane] = v;
    }
    __syncthreads();
    int p = threadIdx.x >> 3, cg = threadIdx.x & 7;
    int pw = pw0 + p;
    if (pw < WP) {
        __nv_bfloat16* dst = g_xp + (((size_t)b * HP + py) * WP + pw) * C2;
        __nv_bfloat162 sq[4], xv[4];
#pragma unroll
        for (int t = 0; t < 4; t++) {
            float v0 = tile[cg * 8 + 2 * t][p];
            float v1 = tile[cg * 8 + 2 * t + 1][p];
            sq[t] = __floats2bfloat162_rn(v0 * v0, v1 * v1);
            xv[t] = __floats2bfloat162_rn(v0, v1);
        }
        *reinterpret_cast<uint4*>(dst + cg * 8) = *reinterpret_cast<const uint4*>(sq);
        *reinterpret_cast<uint4*>(dst + 64 + cg * 8) = *reinterpret_cast<const uint4*>(xv);
    }
}

__global__ void sim_prep_w(const float* __restrict__ sw, const float* __restrict__ tm) {
    int n = blockIdx.x, c = threadIdx.x;
    float csum = 0.f;
#pragma unroll
    for (int p = 0; p < 3; p++)
#pragma unroll
        for (int q = 0; q < 3; q++) {
            size_t idx = (((size_t)n * CC + c) * 3 + p) * 3 + q;
            float w = fabsf(sw[idx]);
            float t = tm[idx];
            csum += w * t * t;
            size_t o = ((size_t)(p * 3 + q) * NN + n) * C2;
            g_wk[o + c] = __float2bfloat16(-w);
            g_wk[o + 64 + c] = __float2bfloat16(2.f * w * t);
        }
    __shared__ float red[64];
    red[c] = csum;
    __syncthreads();
    for (int s = 32; s > 0; s >>= 1) {
        if (c < s) red[c] += red[c + s];
        __syncthreads();
    }
    if (c == 0) g_cn[n] = red[0];
}

// ---------------- descriptor-semantics probe ----------------
__global__ void sim_probe() {
#if HAS_TCGEN05
    __shared__ __align__(1024) char ps[23040];
    __shared__ int err[2];
    uint32_t sb = smem_to_u32(ps);
    int tid = threadIdx.x, wid = tid >> 5, lane = tid & 31;
    if (tid == 0) { err[0] = 0; err[1] = 0; MBARRIER_INIT(sb + 16, 1); }
    if (wid == 0) { TCGEN05_ALLOC(sb + 0, 128); TCGEN05_RELINQUISH_ALLOC_PERMIT(); }
    __syncthreads();
    uint32_t tmem;
    asm volatile("ld.shared.b32 %0, [%1];" : "=r"(tmem) : "r"(sb));

    for (int px = tid; px < 136; px += 128) {
        for (int c = 0; c < 8; c++) {
            __align__(16) __nv_bfloat16 v[8];
#pragma unroll
            for (int e = 0; e < 8; e++) {
                int ch = c * 8 + e;
                v[e] = __float2bfloat16((float)((px * 7 + ch * 13) % 23 - 11));
            }
            *reinterpret_cast<uint4*>(ps + 1024 + px * 128 + ((c ^ (px & 7)) * 16)) =
                *reinterpret_cast<const uint4*>(v);
        }
    }
    for (int n = tid; n < 32; n += 128) {
        for (int c = 0; c < 8; c++) {
            __align__(16) __nv_bfloat16 v[8];
#pragma unroll
            for (int e = 0; e < 8; e++)
                v[e] = __float2bfloat16((c * 8 + e == n) ? 1.f : 0.f);
            *reinterpret_cast<uint4*>(ps + 18432 + n * 128 + ((c ^ (n & 7)) * 16)) =
                *reinterpret_cast<const uint4*>(v);
        }
    }
    __syncthreads();
    FENCE_PROXY_ASYNC();

    const uint32_t idesc = (1u << 4) | (1u << 7) | (1u << 10) | (4u << 17) | (8u << 24);
    uint64_t bdesc = MAKE_SMEM_DESC(sb + 18432);
    for (int cand = 0; cand < 2; cand++) {
        if (tid == 0) {
            uint64_t ad = MAKE_SMEM_DESC(sb + 1024) + 8 + (cand ? (1ull << 48) : 0);
#pragma unroll
            for (int kk = 0; kk < 4; kk++)
                mma_f16_ss(tmem + cand * 64, ad + 2 * kk, bdesc + 2 * kk, idesc, kk > 0);
            TCGEN05_COMMIT(sb + 16);
        }
        __syncthreads();
        MBARRIER_WAIT_PARITY(sb + 16, cand);
        TCGEN05_FENCE_AFTER();
        uint32_t r[32];
        TCGEN05_LD_32X32B_X32(r, tmem + cand * 64);
        TCGEN05_WAIT_LD();
        int px = wid * 32 + lane + 1;
        int bad = 0;
#pragma unroll
        for (int n = 0; n < 32; n++) {
            float expv = (float)((px * 7 + n * 13) % 23 - 11);
            if (__uint_as_float(r[n]) != expv) bad = 1;
        }
        if (bad) atomicAdd(&err[cand], 1);
        __syncthreads();
    }
    if (tid == 0) g_mode = (err[0] == 0) ? 0 : ((err[1] == 0) ? 1 : 2);
    TCGEN05_FENCE_BEFORE();
    __syncthreads();
    if (wid == 0) TCGEN05_DEALLOC(tmem, 128);
#else
    if (threadIdx.x == 0) g_mode = 2;
#endif
}

// ---------------- main conv kernel (persistent, (rp,nh) tiles) ----------------
// Grid = 148 x 320. Warps 0-7: epilogue; tid 256: producer; tid 288: consumer.
// Modes 0/1: tile = (row-pair, nh): 2 rows x N=128 into TMEM buffer ti&1 (256 cols).
//   8 resident A entries (4 rows x 2 kh). 18 substages (pq,kh), B piece 16KB,
//   5-deep ring. A rows 0,1 of next tile prefetched at AFREE (s=11 drain);
//   rows 2,3 after TDONE (needed at s=6). Epilogue overlaps next tile's MMAs.
// Mode 2: R9 schedule (row-pair tiles, N=256, 3x64KB ring, single buffer).
#define SM_BAR_BFULL 16    // 5 x 8B : 16..56
#define SM_BAR_BEMPT 56    // 5 x 8B : 56..96
#define SM_BAR_A0    96
#define SM_BAR_A1    104
#define SM_BAR_AFREE 112
#define SM_BAR_TDONE 120
#define SM_BAR_EPIF0 128
#define SM_BAR_EPIF1 136
#define SM_ABASE     1024
#define A_ENTRY      17408
#define A_DATA       16640            // 130 px * 128B
#define SM_BRING     (SM_ABASE + 8 * A_ENTRY)   // 140288
#define B_STAGE      16384
#define NB           5
// mode-2: stages of 64KB at SM_ABASE (B 32K | A0 16K | A1 16K), 3 deep
#define M2_STAGE     65536
#define M2_OFFA0     32768
#define M2_OFFA1     49152
#define CONV_SMEM    (SM_BRING + NB * B_STAGE)  // 222208
#define NTHREADS     320

#if HAS_TCGEN05
static constexpr uint32_t IDESC_N128 =
    (1u << 4) | (1u << 7) | (1u << 10) | ((128 / 8) << 17) | ((128 / 16) << 24);
static constexpr uint32_t IDESC_N256 =
    (1u << 4) | (1u << 7) | (1u << 10) | ((NN / 8) << 17) | ((128 / 16) << 24);
#endif

__global__ void __launch_bounds__(NTHREADS, 1) sim_conv(
    const __grid_constant__ CUtensorMap tmx130,
    const __grid_constant__ CUtensorMap tmx128,
    const __grid_constant__ CUtensorMap tmw128,
    const __grid_constant__ CUtensorMap tmw256,
    float* __restrict__ out)
{
    extern __shared__ char smem[];
    uint32_t sb = smem_to_u32(smem);
    int tid = threadIdx.x, wid = tid >> 5, lane = tid & 31;
    int bid = blockIdx.x;

    if (tid == 0) {
#pragma unroll
        for (int s = 0; s < NB; s++) {
            MBARRIER_INIT(sb + SM_BAR_BFULL + s * 8, 1);
            MBARRIER_INIT(sb + SM_BAR_BEMPT + s * 8, 1);
        }
        MBARRIER_INIT(sb + SM_BAR_A0, 1);
        MBARRIER_INIT(sb + SM_BAR_A1, 1);
        MBARRIER_INIT(sb + SM_BAR_AFREE, 1);
        MBARRIER_INIT(sb + SM_BAR_TDONE, 1);
        MBARRIER_INIT(sb + SM_BAR_EPIF0, 8);
        MBARRIER_INIT(sb + SM_BAR_EPIF1, 8);
    }

#if HAS_TCGEN05
    if (wid == 0) {
        TCGEN05_ALLOC(sb + 512, 512);
        TCGEN05_RELINQUISH_ALLOC_PERMIT();
    }
    __syncthreads();

    uint32_t tmem;
    asm volatile("ld.shared.b32 %0, [%1];" : "=r"(tmem) : "r"(sb + 512));
    int mode = g_mode;
    int ntiles = (mode < 2) ? (NT2 - bid + NSM - 1) / NSM
                            : (NTILES - bid + NSM - 1) / NSM;

    if (tid == 256) {
        // ================= producer =================
        int gs = 0;
        for (int ti = 0; ti < ntiles; ti++) {
            int t = bid + ti * NSM;
            if (mode < 2) {
                int rp = t >> 1, nh = t & 1;
                int b = rp / (HH / 2), i0 = (rp % (HH / 2)) * 2;
                int zbase = b * HP + i0;
                // rows 0,1: slots free once prev tile's s<=11 MMAs complete
                if (ti > 0) MBARRIER_WAIT_PARITY(sb + SM_BAR_AFREE, (ti - 1) & 1);
                MBARRIER_EXPECT_TX(sb + SM_BAR_A0, 4 * A_DATA);
#pragma unroll
                for (int e = 0; e < 4; e++)
                    TMA_LOAD_3D(sb + SM_ABASE + e * A_ENTRY, &tmx130,
                                64 * (e & 1), 0, zbase + (e >> 1), sb + SM_BAR_A0);
                // B pieces s=0..5
                for (int s = 0; s < 6; s++, gs++) {
                    int st = gs % NB;
                    if (gs >= NB)
                        MBARRIER_WAIT_PARITY(sb + SM_BAR_BEMPT + st * 8,
                                             ((gs - NB) / NB) & 1);
                    int pq = s >> 1, kh = s & 1;
                    MBARRIER_EXPECT_TX(sb + SM_BAR_BFULL + st * 8, B_STAGE);
                    TMA_LOAD_3D(sb + SM_BRING + st * B_STAGE, &tmw128,
                                64 * kh, 128 * nh, pq, sb + SM_BAR_BFULL + st * 8);
                }
                // rows 2,3: slots free once ALL prev tile MMAs complete
                if (ti > 0) MBARRIER_WAIT_PARITY(sb + SM_BAR_TDONE, (ti - 1) & 1);
                MBARRIER_EXPECT_TX(sb + SM_BAR_A1, 4 * A_DATA);
#pragma unroll
                for (int e = 4; e < 8; e++)
                    TMA_LOAD_3D(sb + SM_ABASE + e * A_ENTRY, &tmx130,
                                64 * (e & 1), 0, zbase + (e >> 1), sb + SM_BAR_A1);
                // B pieces s=6..17
                for (int s = 6; s < 18; s++, gs++) {
                    int st = gs % NB;
                    MBARRIER_WAIT_PARITY(sb + SM_BAR_BEMPT + st * 8,
                                         ((gs - NB) / NB) & 1);
                    int pq = s >> 1, kh = s & 1;
                    MBARRIER_EXPECT_TX(sb + SM_BAR_BFULL + st * 8, B_STAGE);
                    TMA_LOAD_3D(sb + SM_BRING + st * B_STAGE, &tmw128,
                                64 * kh, 128 * nh, pq, sb + SM_BAR_BFULL + st * 8);
                }
            } else {
                int b = t / (HH / 2), i0 = (t % (HH / 2)) * 2;
                int zbase = b * HP + i0;
                for (int s = 0; s < 18; s++, gs++) {
                    int st = gs % 3;
                    if (gs >= 3)
                        MBARRIER_WAIT_PARITY(sb + SM_BAR_BEMPT + st * 8,
                                             ((gs - 3) / 3) & 1);
                    int pq = s >> 1, kh = s & 1;
                    int p = pq / 3, q = pq % 3;
                    uint32_t sbase = sb + SM_ABASE + st * M2_STAGE;
                    uint32_t bar = sb + SM_BAR_BFULL + st * 8;
                    MBARRIER_EXPECT_TX(bar, 32768 + 2 * 16384);
                    TMA_LOAD_3D(sbase, &tmw256, 64 * kh, 0, pq, bar);
                    TMA_LOAD_3D(sbase + M2_OFFA0, &tmx128, 64 * kh, q, zbase + p, bar);
                    TMA_LOAD_3D(sbase + M2_OFFA1, &tmx128, 64 * kh, q, zbase + p + 1, bar);
                }
            }
        }
    } else if (tid == 288) {
        // ================= MMA consumer =================
        int gs = 0;
        for (int ti = 0; ti < ntiles; ti++) {
            if (mode < 2) {
                int buf = ti & 1;
                if (ti >= 2) {
                    MBARRIER_WAIT_PARITY(sb + (buf ? SM_BAR_EPIF1 : SM_BAR_EPIF0),
                                         ((ti - 2) >> 1) & 1);
                    TCGEN05_FENCE_AFTER();
                }
                MBARRIER_WAIT_PARITY(sb + SM_BAR_A0, ti & 1);
                uint32_t d0 = tmem + buf * 256;
                uint32_t d1 = d0 + 128;
                for (int s = 0; s < 18; s++, gs++) {
                    if (s == 6) MBARRIER_WAIT_PARITY(sb + SM_BAR_A1, ti & 1);
                    int st = gs % NB;
                    int ph = (gs / NB) & 1;
                    MBARRIER_WAIT_PARITY(sb + SM_BAR_BFULL + st * 8, ph);
                    int pq = s >> 1, kh = s & 1;
                    int p = pq / 3, q = pq % 3;
                    uint64_t bd = MAKE_SMEM_DESC(sb + SM_BRING + st * B_STAGE);
                    uint64_t qadd = (uint64_t)(q * 8) +
                                    (mode == 1 ? ((uint64_t)q << 48) : 0);
                    uint64_t a0 = MAKE_SMEM_DESC(
                        sb + SM_ABASE + (p * 2 + kh) * A_ENTRY) + qadd;
                    uint64_t a1 = MAKE_SMEM_DESC(
                        sb + SM_ABASE + ((p + 1) * 2 + kh) * A_ENTRY) + qadd;
#pragma unroll
                    for (int kk = 0; kk < 4; kk++) {
                        bool acc = !(s == 0 && kk == 0);
                        mma_f16_ss(d0, a0 + 2 * kk, bd + 2 * kk, IDESC_N128, acc);
                        mma_f16_ss(d1, a1 + 2 * kk, bd + 2 * kk, IDESC_N128, acc);
                    }
                    TCGEN05_COMMIT(sb + SM_BAR_BEMPT + st * 8);
                    if (s == 11) TCGEN05_COMMIT(sb + SM_BAR_AFREE);
                }
                TCGEN05_COMMIT(sb + SM_BAR_TDONE);
            } else {
                if (ti > 0) {
                    MBARRIER_WAIT_PARITY(sb + SM_BAR_EPIF0, (ti - 1) & 1);
                    TCGEN05_FENCE_AFTER();
                }
                for (int s = 0; s < 18; s++, gs++) {
                    int st = gs % 3;
                    int ph = (gs / 3) & 1;
                    MBARRIER_WAIT_PARITY(sb + SM_BAR_BFULL + st * 8, ph);
                    uint32_t sbase = sb + SM_ABASE + st * M2_STAGE;
                    uint64_t bd = MAKE_SMEM_DESC(sbase);
                    uint64_t a0 = MAKE_SMEM_DESC(sbase + M2_OFFA0);
                    uint64_t a1 = MAKE_SMEM_DESC(sbase + M2_OFFA1);
#pragma unroll
                    for (int kk = 0; kk < 4; kk++) {
                        bool acc = !(s == 0 && kk == 0);
                        mma_f16_ss(tmem,       a0 + 2 * kk, bd + 2 * kk, IDESC_N256, acc);
                        mma_f16_ss(tmem + 256, a1 + 2 * kk, bd + 2 * kk, IDESC_N256, acc);
                    }
                    TCGEN05_COMMIT(sb + SM_BAR_BEMPT + st * 8);
                }
                TCGEN05_COMMIT(sb + SM_BAR_TDONE);
            }
        }
    } else if (wid < 8) {
        // ================= epilogue workers =================
        int r = wid >> 2;               // output row within pair
        int jj = (wid & 3) * 32 + lane; // pixel (TMEM lane)
        for (int ti = 0; ti < ntiles; ti++) {
            int t = bid + ti * NSM;
            if (mode < 2) {
                int rp = t >> 1, nh = t & 1;
                int b = rp / (HH / 2), i0 = (rp % (HH / 2)) * 2;
                int i = i0 + r;
                int buf = ti & 1;
                MBARRIER_WAIT_PARITY(sb + SM_BAR_TDONE, ti & 1);
                TCGEN05_FENCE_AFTER();
                uint32_t dbase = tmem + buf * 256 + r * 128;
                for (int ch = 0; ch < 4; ch++) {
                    uint32_t reg[32];
                    TCGEN05_LD_32X32B_X32(reg, dbase + ch * 32);
                    TCGEN05_WAIT_LD();
                    if (jj < WW) {
                        int n0 = nh * 128 + ch * 32;
                        float* po = out + (((size_t)(b * NN + n0)) * HH + i) * WW + jj;
#pragma unroll
                        for (int c = 0; c < 32; c++)
                            po[(size_t)c * (HH * WW)] =
                                __uint_as_float(reg[c]) - __ldg(&g_cn[n0 + c]);
                    }
                }
                TCGEN05_FENCE_BEFORE();
                if (lane == 0)
                    MBARRIER_ARRIVE(sb + (buf ? SM_BAR_EPIF1 : SM_BAR_EPIF0));
            } else {
                int b = t / (HH / 2), i0 = (t % (HH / 2)) * 2;
                int i = i0 + r;
                MBARRIER_WAIT_PARITY(sb + SM_BAR_TDONE, ti & 1);
                TCGEN05_FENCE_AFTER();
                uint32_t dbase = tmem + r * 256;
                for (int c0 = 0; c0 < NN; c0 += 32) {
                    uint32_t reg[32];
                    TCGEN05_LD_32X32B_X32(reg, dbase + c0);
                    TCGEN05_WAIT_LD();
                    if (jj < WW) {
                        float* po = out + (((size_t)(b * NN + c0)) * HH + i) * WW + jj;
#pragma unroll
                        for (int c = 0; c < 32; c++)
                            po[(size_t)c * (HH * WW)] =
                                __uint_as_float(reg[c]) - __ldg(&g_cn[c0 + c]);
                    }
                }
                TCGEN05_FENCE_BEFORE();
                if (lane == 0) MBARRIER_ARRIVE(sb + SM_BAR_EPIF0);
            }
        }
    }

    __syncthreads();
    if (wid == 0) TCGEN05_DEALLOC(tmem, 512);

#else
    // -------- compile-only fallback for plain sm_103 --------
    __syncthreads();
    int ntiles = (NTILES - bid + NSM - 1) / NSM;
    const float* cn_g = g_cn;
    for (int ti = 0; ti < ntiles; ti++) {
        int t = bid + ti * NSM;
        int b = t / (HH / 2), i0 = (t % (HH / 2)) * 2;
        for (int e = tid; e < 2 * NN * WW; e += NTHREADS) {
            int j = e % WW;
            int n = (e / WW) % NN;
            int r = e / (WW * NN);
            int i = i0 + r;
            float acc = 0.f;
            for (int p = 0; p < 3; p++)
                for (int q = 0; q < 3; q++) {
                    const __nv_bfloat16* a =
                        g_xp + (((size_t)b * HP + (i + p)) * WP + (j + q)) * C2;
                    const __nv_bfloat16* wv = g_wk + ((size_t)(p * 3 + q) * NN + n) * C2;
                    for (int c = 0; c < C2; c++)
                        acc += __bfloat162float(a[c]) * __bfloat162float(wv[c]);
                }
            out[(((size_t)(b * NN + n)) * HH + i) * WW + j] = acc - cn_g[n];
        }
    }
#endif
}

// ---------------- host launcher ----------------
typedef CUresult (*PFN_encodeTiled)(
    CUtensorMap*, CUtensorMapDataType, cuuint32_t, void*,
    const cuuint64_t*, const cuuint64_t*, const cuuint32_t*, const cuuint32_t*,
    CUtensorMapInterleave, CUtensorMapSwizzle, CUtensorMapL2promotion,
    CUtensorMapFloatOOBfill);

extern "C" void kernel_launch(void* const* d_in, const int* in_sizes, int n_in,
                              void* d_out, int out_size) {
    const float* x  = (const float*)d_in[0];
    const float* sw = (const float*)d_in[1];
    const float* tm = (const float*)d_in[2];
    float* out = (float*)d_out;

    static PFN_encodeTiled enc = nullptr;
    if (!enc) {
        void* fp = nullptr;
        cudaDriverEntryPointQueryResult qr;
        cudaGetDriverEntryPoint("cuTensorMapEncodeTiled", &fp, cudaEnableDefault, &qr);
        enc = (PFN_encodeTiled)fp;
    }
    if (!enc) return;

    void* xp_ptr = nullptr;
    void* wk_ptr = nullptr;
    cudaGetSymbolAddress(&xp_ptr, g_xp);
    cudaGetSymbolAddress(&wk_ptr, g_wk);

    CUtensorMap tmx130, tmx128, tmw128, tmw256;
    {
        cuuint64_t dims[3]    = {C2, WP, (cuuint64_t)BB * HP};
        cuuint64_t strides[2] = {(cuuint64_t)C2 * 2, (cuuint64_t)WP * C2 * 2};
        cuuint32_t es[3]      = {1, 1, 1};
        cuuint32_t box130[3]  = {64, 130, 1};
        cuuint32_t box128[3]  = {64, 128, 1};
        enc(&tmx130, CU_TENSOR_MAP_DATA_TYPE_BFLOAT16, 3, xp_ptr, dims, strides, box130, es,
            CU_TENSOR_MAP_INTERLEAVE_NONE, CU_TENSOR_MAP_SWIZZLE_128B,
            CU_TENSOR_MAP_L2_PROMOTION_L2_128B, CU_TENSOR_MAP_FLOAT_OOB_FILL_NONE);
        enc(&tmx128, CU_TENSOR_MAP_DATA_TYPE_BFLOAT16, 3, xp_ptr, dims, strides, box128, es,
            CU_TENSOR_MAP_INTERLEAVE_NONE, CU_TENSOR_MAP_SWIZZLE_128B,
            CU_TENSOR_MAP_L2_PROMOTION_L2_128B, CU_TENSOR_MAP_FLOAT_OOB_FILL_NONE);
    }
    {
        cuuint64_t dims[3]    = {C2, NN, 9};
        cuuint64_t strides[2] = {(cuuint64_t)C2 * 2, (cuuint64_t)NN * C2 * 2};
        cuuint32_t es[3]      = {1, 1, 1};
        cuuint32_t boxh[3]    = {64, 128, 1};
        cuuint32_t boxf[3]    = {64, 256, 1};
        enc(&tmw128, CU_TENSOR_MAP_DATA_TYPE_BFLOAT16, 3, wk_ptr, dims, strides, boxh, es,
            CU_TENSOR_MAP_INTERLEAVE_NONE, CU_TENSOR_MAP_SWIZZLE_128B,
            CU_TENSOR_MAP_L2_PROMOTION_L2_128B, CU_TENSOR_MAP_FLOAT_OOB_FILL_NONE);
        enc(&tmw256, CU_TENSOR_MAP_DATA_TYPE_BFLOAT16, 3, wk_ptr, dims, strides, boxf, es,
            CU_TENSOR_MAP_INTERLEAVE_NONE, CU_TENSOR_MAP_SWIZZLE_128B,
            CU_TENSOR_MAP_L2_PROMOTION_L2_128B, CU_TENSOR_MAP_FLOAT_OOB_FILL_NONE);
    }

    cudaFuncSetAttribute(sim_conv, cudaFuncAttributeMaxDynamicSharedMemorySize, CONV_SMEM);

    sim_fill_xp<<<dim3(5, HP, BB), 256>>>(x);
    sim_prep_w<<<NN, 64>>>(sw, tm);
    sim_probe<<<1, 128>>>();
    sim_conv<<<NSM, NTHREADS, CONV_SMEM>>>(tmx130, tmx128, tmw128, tmw256, out);
}